// round 11
// baseline (speedup 1.0000x reference)
#include <cuda_runtime.h>
#include <math.h>

#define B     4
#define T     16
#define HID   64
#define HW    64
#define PLANE 4096   // 64*64

__device__ float g_buf0[(size_t)B * T * HID * PLANE];
__device__ float g_buf1[(size_t)B * T * HID * PLANE];
__device__ float g_c[3][(size_t)B * HID * PLANE];   // per-layer (layers run concurrently)

typedef unsigned long long ull;

__device__ __forceinline__ float tanh_fast(float x) {
    float y;
    asm("tanh.approx.f32 %0, %1;" : "=f"(y) : "f"(x));
    return y;
}
__device__ __forceinline__ float sigm(float v) {
    return fmaf(tanh_fast(0.5f * v), 0.5f, 0.5f);
}
__device__ __forceinline__ ull splat2(float a) {
    ull r;
    asm("mov.b64 %0, {%1, %1};" : "=l"(r) : "f"(a));
    return r;
}
__device__ __forceinline__ void fma2(ull& d, ull a, ull b) {
    asm("fma.rn.f32x2 %0, %1, %2, %0;" : "+l"(d) : "l"(a), "l"(b));
}
__device__ __forceinline__ void unpack2(ull v, float& lo, float& hi) {
    asm("mov.b64 {%0, %1}, %2;" : "=f"(lo), "=f"(hi) : "l"(v));
}
__device__ __forceinline__ void cp16(void* dst_smem, const void* src) {
    unsigned sd = (unsigned)__cvta_generic_to_shared(dst_smem);
    asm volatile("cp.async.cg.shared.global [%0], [%1], 16;" :: "r"(sd), "l"(src) : "memory");
}
__device__ __forceinline__ void cp_commit() {
    asm volatile("cp.async.commit_group;" ::: "memory");
}
template <int N> __device__ __forceinline__ void cp_wait() {
    asm volatile("cp.async.wait_group %0;" :: "n"(N) : "memory");
}

// Padded smem activation row stride: 4 left pad + 64 data + 4 right pad (floats).
#define ASTRIDE 72

// Accumulate one staged plane: 2 ch x 4 gates(packed f32x2) x 8 px.
// Zero pads + zeroed OOB rows => no predication anywhere in the hot loop.
template <int DIL>
__device__ __forceinline__ void accum_stage(
    const float* __restrict__ stg,               // stage base (row 0, incl. left pad)
    const ulonglong2* __restrict__ w0, const ulonglong2* __restrict__ w1,
    int r0, int x0, ull acc[2][2][8])
{
#pragma unroll
    for (int ky = 0; ky < 3; ky++) {
        const float* srow = stg + (r0 + ky * DIL) * ASTRIDE + 4;  // data col 0

        float vals[8 + 2 * DIL];
        {
            float4 m0 = *(const float4*)(srow + x0);
            float4 m1 = *(const float4*)(srow + x0 + 4);
            vals[DIL + 0] = m0.x; vals[DIL + 1] = m0.y;
            vals[DIL + 2] = m0.z; vals[DIL + 3] = m0.w;
            vals[DIL + 4] = m1.x; vals[DIL + 5] = m1.y;
            vals[DIL + 6] = m1.z; vals[DIL + 7] = m1.w;
        }
        if (DIL == 1) {
            vals[0] = srow[x0 - 1];
            vals[9] = srow[x0 + 8];
        } else if (DIL == 2) {
            float2 l = *(const float2*)(srow + x0 - 2);
            float2 r = *(const float2*)(srow + x0 + 8);
            vals[0] = l.x; vals[1] = l.y;
            vals[10] = r.x; vals[11] = r.y;
        } else {  // DIL == 4
            float4 l = *(const float4*)(srow + x0 - 4);
            float4 r = *(const float4*)(srow + x0 + 8);
            vals[0] = l.x; vals[1] = l.y; vals[2] = l.z; vals[3] = l.w;
            vals[12] = r.x; vals[13] = r.y; vals[14] = r.z; vals[15] = r.w;
        }

        ull vp[8 + 2 * DIL];
#pragma unroll
        for (int j = 0; j < 8 + 2 * DIL; j++) vp[j] = splat2(vals[j]);

#pragma unroll
        for (int kx = 0; kx < 3; kx++) {
            const ulonglong2 wa = w0[ky * 3 + kx];
            const ulonglong2 wb = w1[ky * 3 + kx];
#pragma unroll
            for (int px = 0; px < 8; px++) {
                const ull v = vp[px + kx * DIL];
                fma2(acc[0][0][px], wa.x, v);
                fma2(acc[0][1][px], wa.y, v);
                fma2(acc[1][0][px], wb.x, v);
                fma2(acc[1][1][px], wb.y, v);
            }
        }
    }
}

// Block: 128 threads = 16 rows x 64 cols; thread: 2 out-channels x 8 px.
// Activations double-buffered in smem via cp.async; weights staged in smem.
template <int LAYER, int CIN_X, int DIL>
__global__ void __launch_bounds__(128, 4) lstm_step(
    const float* __restrict__ x_in,
    const float* __restrict__ gw,     // [4*HID][CC][3][3]
    const float* __restrict__ gb,     // [4*HID]
    const float* __restrict__ rw,     // [HID][CIN_X] (layer 0) or null
    const float* __restrict__ rb,
    float* __restrict__ out_final,
    int t)
{
    constexpr int CC     = CIN_X + HID;
    constexpr int ROWS_S = 16 + 2 * DIL;
    constexpr int STAGE  = ROWS_S * ASTRIDE;     // floats per stage

    extern __shared__ float smem[];
    float4* ws4 = (float4*)smem;                 // [2][CC*9] -> (wi,wf,wg,wo)
    float*  rws = smem + 2 * CC * 9 * 4;         // [2][CIN_X] flat (layer 0)
    float*  act = rws + 64;                      // 2 stages x STAGE floats (16B aligned)

    const int tid      = threadIdx.x;
    const int ytile    = blockIdx.x;             // 4 tiles of 16 rows
    const int co_group = blockIdx.y;             // 32 groups of 2 ch
    const int b        = blockIdx.z;
    const int r0       = tid >> 3;               // 0..15 (row within tile)
    const int row      = ytile * 16 + r0;
    const int x0       = (tid & 7) << 3;         // 8 px per thread
    const int rowbase  = ytile * 16;

    // Stage weights (gate-vectorized).
    {
        float* wsf = (float*)ws4;
        for (int i = tid; i < 2 * CC * 9 * 4; i += 128) {
            int g  = i & 3;
            int r  = i >> 2;
            int cl = r / (CC * 9);
            int ck = r - cl * CC * 9;
            wsf[i] = gw[(size_t)(g * HID + co_group * 2 + cl) * (CC * 9) + ck];
        }
    }
    if (LAYER == 0 && tid < 2 * CIN_X)
        rws[tid] = rw[((co_group * 2 + tid / CIN_X) * CIN_X) + (tid % CIN_X)];

    // Zero both activation stages (pads + OOB halo rows stay zero forever).
    for (int i = tid; i < 2 * STAGE / 4; i += 128)
        ((float4*)act)[i] = make_float4(0.f, 0.f, 0.f, 0.f);
    __syncthreads();

    const float* seq_in  = (LAYER == 0) ? x_in : ((LAYER == 1) ? g_buf0 : g_buf1);
    float*       seq_out = (LAYER == 0) ? g_buf0 : ((LAYER == 1) ? g_buf1 : out_final);

    const float* xt = seq_in + (size_t)(b * T + t) * CIN_X * PLANE;
    const float* hp = seq_out + (size_t)(b * T + (t - 1)) * HID * PLANE;  // valid t>0
    const int ctot  = (t > 0) ? CC : CIN_X;

    auto plane_ptr = [&](int ci) -> const float* {
        return (ci < CIN_X) ? (xt + (size_t)ci * PLANE)
                            : (hp + (size_t)(ci - CIN_X) * PLANE);
    };
    auto load_stage = [&](float* dst, const float* plane) {
        for (int it = tid; it < ROWS_S * 16; it += 128) {
            int r  = it >> 4;
            int c  = it & 15;
            int rg = rowbase - DIL + r;
            if (rg >= 0 && rg < HW)
                cp16(dst + r * ASTRIDE + 4 + c * 4, plane + rg * HW + c * 4);
        }
    };

    ull acc[2][2][8];
#pragma unroll
    for (int cl = 0; cl < 2; cl++)
#pragma unroll
        for (int gp = 0; gp < 2; gp++)
#pragma unroll
            for (int px = 0; px < 8; px++) acc[cl][gp][px] = 0ULL;

    const ulonglong2* w0 = (const ulonglong2*)ws4;
    const ulonglong2* w1 = (const ulonglong2*)(ws4 + CC * 9);

    // Prologue: stage plane 0.
    load_stage(act, plane_ptr(0));
    cp_commit();

    for (int ci = 0; ci < ctot; ci++) {
        const int nxt = ci + 1;
        if (nxt < ctot) {
            load_stage(act + (nxt & 1) * STAGE, plane_ptr(nxt));
            cp_commit();
            cp_wait<1>();
        } else {
            cp_wait<0>();
        }
        __syncthreads();                       // stage ci visible to all warps
        accum_stage<DIL>(act + (ci & 1) * STAGE, w0 + ci * 9, w1 + ci * 9,
                         r0, x0, acc);
        __syncthreads();                       // done reading before overwrite
    }

    // Residual
    float res[2][8];
    if (LAYER == 0) {
#pragma unroll
        for (int cl = 0; cl < 2; cl++) {
            float rbv = __ldg(rb + co_group * 2 + cl);
#pragma unroll
            for (int px = 0; px < 8; px++) res[cl][px] = rbv;
        }
        const float* p = xt + row * HW + x0;
        for (int ci = 0; ci < CIN_X; ci++, p += PLANE) {
            float4 p0 = __ldg((const float4*)p);
            float4 p1 = __ldg((const float4*)(p + 4));
#pragma unroll
            for (int cl = 0; cl < 2; cl++) {
                float w = rws[cl * CIN_X + ci];
                res[cl][0] = fmaf(w, p0.x, res[cl][0]);
                res[cl][1] = fmaf(w, p0.y, res[cl][1]);
                res[cl][2] = fmaf(w, p0.z, res[cl][2]);
                res[cl][3] = fmaf(w, p0.w, res[cl][3]);
                res[cl][4] = fmaf(w, p1.x, res[cl][4]);
                res[cl][5] = fmaf(w, p1.y, res[cl][5]);
                res[cl][6] = fmaf(w, p1.z, res[cl][6]);
                res[cl][7] = fmaf(w, p1.w, res[cl][7]);
            }
        }
    } else {
#pragma unroll
        for (int cl = 0; cl < 2; cl++) {
            const float* p = xt + (size_t)(co_group * 2 + cl) * PLANE + row * HW + x0;
            float4 p0 = __ldg((const float4*)p);
            float4 p1 = __ldg((const float4*)(p + 4));
            res[cl][0] = p0.x; res[cl][1] = p0.y; res[cl][2] = p0.z; res[cl][3] = p0.w;
            res[cl][4] = p1.x; res[cl][5] = p1.y; res[cl][6] = p1.z; res[cl][7] = p1.w;
        }
    }

#pragma unroll
    for (int cl = 0; cl < 2; cl++) {
        const int co = co_group * 2 + cl;
        float gbv[4];
#pragma unroll
        for (int g = 0; g < 4; g++) gbv[g] = __ldg(gb + g * HID + co);

        float* cptr = g_c[LAYER] + (size_t)(b * HID + co) * PLANE + row * HW + x0;
        float* optr = seq_out + ((size_t)(b * T + t) * HID + co) * PLANE + row * HW + x0;

        float co_a[8];
        if (t > 0) {
            float4 c0 = *(const float4*)cptr;
            float4 c1 = *(const float4*)(cptr + 4);
            co_a[0] = c0.x; co_a[1] = c0.y; co_a[2] = c0.z; co_a[3] = c0.w;
            co_a[4] = c1.x; co_a[5] = c1.y; co_a[6] = c1.z; co_a[7] = c1.w;
        } else {
#pragma unroll
            for (int px = 0; px < 8; px++) co_a[px] = 0.f;
        }

        float cn_a[8], ho_a[8];
#pragma unroll
        for (int px = 0; px < 8; px++) {
            float aI, aF, aG, aO;
            unpack2(acc[cl][0][px], aI, aF);
            unpack2(acc[cl][1][px], aG, aO);
            float iv = sigm(aI + gbv[0]);
            float fv = sigm(aF + gbv[1]);
            float gv = tanh_fast(aG + gbv[2]);
            float ov = sigm(aO + gbv[3]);
            float cn = fv * co_a[px] + iv * gv;
            cn_a[px] = cn;
            ho_a[px] = ov * tanh_fast(cn) + res[cl][px];
        }
        *(float4*)cptr       = make_float4(cn_a[0], cn_a[1], cn_a[2], cn_a[3]);
        *(float4*)(cptr + 4) = make_float4(cn_a[4], cn_a[5], cn_a[6], cn_a[7]);
        *(float4*)optr       = make_float4(ho_a[0], ho_a[1], ho_a[2], ho_a[3]);
        *(float4*)(optr + 4) = make_float4(ho_a[4], ho_a[5], ho_a[6], ho_a[7]);
    }
}

static constexpr int smem_bytes(int cin_x, int dil) {
    int cc = cin_x + HID;
    return cc * 9 * 2 * 16 + 256 + 2 * (16 + 2 * dil) * ASTRIDE * 4;
}

extern "C" void kernel_launch(void* const* d_in, const int* in_sizes, int n_in,
                              void* d_out, int out_size)
{
    (void)in_sizes; (void)n_in; (void)out_size;
    const float* x   = (const float*)d_in[0];
    const float* gw0 = (const float*)d_in[1];
    const float* gb0 = (const float*)d_in[2];
    const float* gw1 = (const float*)d_in[3];
    const float* gb1 = (const float*)d_in[4];
    const float* gw2 = (const float*)d_in[5];
    const float* gb2 = (const float*)d_in[6];
    const float* rw0 = (const float*)d_in[7];
    const float* rb0 = (const float*)d_in[8];
    float* out = (float*)d_out;

    constexpr int SM0 = smem_bytes(32, 1);
    constexpr int SM1 = smem_bytes(64, 2);
    constexpr int SM2 = smem_bytes(64, 4);

    static cudaStream_t s1 = nullptr, s2 = nullptr;
    static cudaEvent_t  e0[T], e1[T], f1, f2;
    if (s1 == nullptr) {
        cudaFuncSetAttribute(lstm_step<0, 32, 1>,
                             cudaFuncAttributeMaxDynamicSharedMemorySize, SM0);
        cudaFuncSetAttribute(lstm_step<1, 64, 2>,
                             cudaFuncAttributeMaxDynamicSharedMemorySize, SM1);
        cudaFuncSetAttribute(lstm_step<2, 64, 4>,
                             cudaFuncAttributeMaxDynamicSharedMemorySize, SM2);
        cudaStreamCreateWithFlags(&s1, cudaStreamNonBlocking);
        cudaStreamCreateWithFlags(&s2, cudaStreamNonBlocking);
        for (int t = 0; t < T; t++) {
            cudaEventCreateWithFlags(&e0[t], cudaEventDisableTiming);
            cudaEventCreateWithFlags(&e1[t], cudaEventDisableTiming);
        }
        cudaEventCreateWithFlags(&f1, cudaEventDisableTiming);
        cudaEventCreateWithFlags(&f2, cudaEventDisableTiming);
    }

    dim3 grid(4, 32, B);
    for (int t = 0; t < T; t++) {
        lstm_step<0, 32, 1><<<grid, 128, SM0, 0>>>(x, gw0, gb0, rw0, rb0, out, t);
        cudaEventRecord(e0[t], 0);
        cudaStreamWaitEvent(s1, e0[t], 0);
        lstm_step<1, 64, 2><<<grid, 128, SM1, s1>>>(x, gw1, gb1, nullptr, nullptr, out, t);
        cudaEventRecord(e1[t], s1);
        cudaStreamWaitEvent(s2, e1[t], 0);
        lstm_step<2, 64, 4><<<grid, 128, SM2, s2>>>(x, gw2, gb2, nullptr, nullptr, out, t);
    }
    cudaEventRecord(f1, s1);
    cudaEventRecord(f2, s2);
    cudaStreamWaitEvent(0, f1, 0);
    cudaStreamWaitEvent(0, f2, 0);
}